// round 10
// baseline (speedup 1.0000x reference)
#include <cuda_runtime.h>
#include <math.h>
#include <stdint.h>

#define BB 8
#define CH 64
#define HH 128
#define WW 128

typedef unsigned long long u64;

// ---------------- scratch (device globals; no allocation allowed) ----------
__device__ float g_x_nhwc[BB*HH*WW*CH];   // x transposed to NHWC
__device__ float g_xh_nhwc[BB*HH*WW*CH];  // horizontal-pass output, NHWC
__device__ float g_omh[BB*HH*WW*12];      // dy0,dx0,dy1,dx1,dy2,dx2,m0,m1,m2,pad
__device__ float g_omv[BB*HH*WW*12];
// Packed weight images: [pass][k][c][64 floats]; row = 32 u64 out-pairs:
// u64 pos = i2*16 + og*2 + t holds (w[2jg], w[2jg+1]), jg = og*4 + i2*2 + t
__device__ __align__(16) float g_wB[2][12288];

// ---------------- f32x2 packed helpers (Blackwell FFMA2) -------------------
static __device__ __forceinline__ u64 pk2(float a, float b) {
    u64 r; asm("mov.b64 %0, {%1,%2};" : "=l"(r) : "f"(a), "f"(b)); return r;
}
static __device__ __forceinline__ void upk2(u64 v, float &a, float &b) {
    asm("mov.b64 {%0,%1}, %2;" : "=f"(a), "=f"(b) : "l"(v));
}
static __device__ __forceinline__ u64 ffma2(u64 a, u64 b, u64 c) {
    u64 d; asm("fma.rn.f32x2 %0, %1, %2, %3;" : "=l"(d) : "l"(a), "l"(b), "l"(c)); return d;
}
static __device__ __forceinline__ u64 fmul2(u64 a, u64 b) {
    u64 d; asm("mul.rn.f32x2 %0, %1, %2;" : "=l"(d) : "l"(a), "l"(b)); return d;
}
static __device__ __forceinline__ float f4c(const float4 &v, int i) {
    return i == 0 ? v.x : (i == 1 ? v.y : (i == 2 ? v.z : v.w));
}

// ---------------- K-1: weight repack (runs once, tiny) ---------------------
__global__ __launch_bounds__(256) void prep_weights(
    const float* __restrict__ wh, const float* __restrict__ wv)
{
    int i = blockIdx.x*256 + threadIdx.x;
    if (i >= 24576) return;
    int pass = i / 12288;
    int r = i % 12288;
    int k = r / 4096;
    int rr = r % 4096;
    int c = rr / 64;
    int f = rr % 64;
    int pos = f >> 1, e = f & 1;
    int i2 = pos >> 4, og = (pos >> 1) & 7, t = pos & 1;
    int jg = og*4 + i2*2 + t;
    int o = 2*jg + e;
    const float* w = pass ? wv : wh;
    g_wB[pass][r] = w[o*192 + c*3 + k];
}

// ---------------- K0: NCHW -> NHWC transpose -------------------------------
__global__ __launch_bounds__(256) void transpose_kernel(const float* __restrict__ in) {
    __shared__ float tile[CH][33];
    int n = blockIdx.z, y = blockIdx.y, x0 = blockIdx.x * 32;
    int tx = threadIdx.x, ty = threadIdx.y;
    #pragma unroll
    for (int c = ty; c < CH; c += 8)
        tile[c][tx] = in[(((size_t)n*CH + c)*HH + y)*WW + x0 + tx];
    __syncthreads();
    int t = ty*32 + tx;
    #pragma unroll
    for (int i = 0; i < 8; i++) {
        int idx = t + i*256;
        int px = idx >> 6, c = idx & 63;
        g_x_nhwc[(((size_t)n*HH + y)*WW + x0 + px)*CH + c] = tile[c][px];
    }
}

// ---------------- K1: offsets + masks, 2 px (adjacent rows)/thread ---------
__global__ __launch_bounds__(256, 2) void offmask_kernel(
    const float* __restrict__ woh, const float* __restrict__ boh,
    const float* __restrict__ wmh, const float* __restrict__ bmh,
    const float* __restrict__ wov, const float* __restrict__ bov,
    const float* __restrict__ wmv, const float* __restrict__ bmv)
{
    __shared__ float ws[64*6*12];
    int tid = threadIdx.x;
    for (int i = tid; i < 64*6*12; i += 256) {
        int o = i % 12, j = (i/12) % 6, c = i/72;
        float v = 0.f;
        if (o < 6)      v = (j < 3) ? woh[o*192 + c*3 + j] : wov[o*192 + c*3 + (j-3)];
        else if (o < 9) v = (j < 3) ? wmh[(o-6)*192 + c*3 + j] : wmv[(o-6)*192 + c*3 + (j-3)];
        ws[i] = v;
    }
    __syncthreads();

    int x = tid & 127;
    int pairidx = blockIdx.x*2 + (tid >> 7);
    int row0 = pairidx*2;
    int y = row0 & 127;
    size_t p0 = (size_t)row0*WW + x;
    size_t p1 = p0 + WW;

    u64 H0a=0,H0b=0,H0c=0,H0d=0, V0a=0,V0b=0,V0c=0,V0d=0;
    u64 H1a=0,H1b=0,H1c=0,H1d=0, V1a=0,V1b=0,V1c=0,V1d=0;
    float H0e=0.f, V0e=0.f, H1e=0.f, V1e=0.f;

    const float* pc0 = g_x_nhwc + p0*CH;
    const float* pc1 = g_x_nhwc + p1*CH;
    bool hl = x > 0, hr = x < WW-1;
    bool vu = y > 0, vd = (y + 2) < HH;
    const float* pl0 = pc0 - CH;
    const float* pr0 = pc0 + CH;
    const float* pl1 = pc1 - CH;
    const float* pr1 = pc1 + CH;
    const float* pu  = pc0 - (size_t)WW*CH;
    const float* pd  = pc1 + (size_t)WW*CH;
    const float4 Z = make_float4(0.f,0.f,0.f,0.f);

    for (int c4 = 0; c4 < 16; c4++) {
        float4 fc0 = *(const float4*)(pc0 + c4*4);
        float4 fc1 = *(const float4*)(pc1 + c4*4);
        float4 fl0 = hl ? *(const float4*)(pl0 + c4*4) : Z;
        float4 fr0 = hr ? *(const float4*)(pr0 + c4*4) : Z;
        float4 fl1 = hl ? *(const float4*)(pl1 + c4*4) : Z;
        float4 fr1 = hr ? *(const float4*)(pr1 + c4*4) : Z;
        float4 fu  = vu ? *(const float4*)(pu  + c4*4) : Z;
        float4 fd  = vd ? *(const float4*)(pd  + c4*4) : Z;
        #pragma unroll
        for (int cc = 0; cc < 4; cc++) {
            int c = c4*4 + cc;
            float h0[3] = { f4c(fl0,cc), f4c(fc0,cc), f4c(fr0,cc) };
            float h1[3] = { f4c(fl1,cc), f4c(fc1,cc), f4c(fr1,cc) };
            float v0[3] = { f4c(fu,cc),  f4c(fc0,cc), f4c(fc1,cc) };
            float v1[3] = { f4c(fc0,cc), f4c(fc1,cc), f4c(fd,cc)  };
            #pragma unroll
            for (int j = 0; j < 3; j++) {
                const float* wb = &ws[(c*6 + j)*12];
                ulonglong2 W0 = *(const ulonglong2*)(wb);
                ulonglong2 W1 = *(const ulonglong2*)(wb + 4);
                float w8 = wb[8];
                u64 s0 = pk2(h0[j], h0[j]);
                H0a = ffma2(s0, W0.x, H0a); H0b = ffma2(s0, W0.y, H0b);
                H0c = ffma2(s0, W1.x, H0c); H0d = ffma2(s0, W1.y, H0d);
                H0e = fmaf(h0[j], w8, H0e);
                u64 s1 = pk2(h1[j], h1[j]);
                H1a = ffma2(s1, W0.x, H1a); H1b = ffma2(s1, W0.y, H1b);
                H1c = ffma2(s1, W1.x, H1c); H1d = ffma2(s1, W1.y, H1d);
                H1e = fmaf(h1[j], w8, H1e);

                const float* ub = &ws[(c*6 + j + 3)*12];
                ulonglong2 U0 = *(const ulonglong2*)(ub);
                ulonglong2 U1 = *(const ulonglong2*)(ub + 4);
                float u8 = ub[8];
                u64 t0 = pk2(v0[j], v0[j]);
                V0a = ffma2(t0, U0.x, V0a); V0b = ffma2(t0, U0.y, V0b);
                V0c = ffma2(t0, U1.x, V0c); V0d = ffma2(t0, U1.y, V0d);
                V0e = fmaf(v0[j], u8, V0e);
                u64 t1 = pk2(v1[j], v1[j]);
                V1a = ffma2(t1, U0.x, V1a); V1b = ffma2(t1, U0.y, V1b);
                V1c = ffma2(t1, U1.x, V1c); V1d = ffma2(t1, U1.y, V1d);
                V1e = fmaf(v1[j], u8, V1e);
            }
        }
    }

    float b0 = __ldg(boh+0), b1 = __ldg(boh+1), b2 = __ldg(boh+2);
    float b3 = __ldg(boh+3), b4 = __ldg(boh+4), b5 = __ldg(boh+5);
    float c0 = __ldg(bov+0), c1 = __ldg(bov+1), c2 = __ldg(bov+2);
    float c3 = __ldg(bov+3), c4b = __ldg(bov+4), c5 = __ldg(bov+5);
    float mb0 = __ldg(bmh+0), mb1 = __ldg(bmh+1), mb2 = __ldg(bmh+2);
    float nb0 = __ldg(bmv+0), nb1 = __ldg(bmv+1), nb2 = __ldg(bmv+2);

    #pragma unroll
    for (int r = 0; r < 2; r++) {
        float A[9], V[9];
        if (r == 0) {
            upk2(H0a,A[0],A[1]); upk2(H0b,A[2],A[3]); upk2(H0c,A[4],A[5]);
            upk2(H0d,A[6],A[7]); A[8]=H0e;
            upk2(V0a,V[0],V[1]); upk2(V0b,V[2],V[3]); upk2(V0c,V[4],V[5]);
            upk2(V0d,V[6],V[7]); V[8]=V0e;
        } else {
            upk2(H1a,A[0],A[1]); upk2(H1b,A[2],A[3]); upk2(H1c,A[4],A[5]);
            upk2(H1d,A[6],A[7]); A[8]=H1e;
            upk2(V1a,V[0],V[1]); upk2(V1b,V[2],V[3]); upk2(V1c,V[4],V[5]);
            upk2(V1d,V[6],V[7]); V[8]=V1e;
        }
        size_t p = r ? p1 : p0;
        float mh0 = 1.f/(1.f + expf(-(A[6] + mb0)));
        float mh1 = 1.f/(1.f + expf(-(A[7] + mb1)));
        float mh2 = 1.f/(1.f + expf(-(A[8] + mb2)));
        float mv0 = 1.f/(1.f + expf(-(V[6] + nb0)));
        float mv1 = 1.f/(1.f + expf(-(V[7] + nb1)));
        float mv2 = 1.f/(1.f + expf(-(V[8] + nb2)));
        float* oh = g_omh + p*12;
        *(float4*)(oh+0) = make_float4(A[0]+b0, A[1]+b1, A[2]+b2, A[3]+b3);
        *(float4*)(oh+4) = make_float4(A[4]+b4, A[5]+b5, mh0, mh1);
        oh[8] = mh2;
        float* ov = g_omv + p*12;
        *(float4*)(ov+0) = make_float4(V[0]+c0, V[1]+c1, V[2]+c2, V[3]+c3);
        *(float4*)(ov+4) = make_float4(V[4]+c4b, V[5]+c5, mv0, mv1);
        ov[8] = mv2;
    }
}

// ---------------- K2/K3: deformable axial pass (software-pipelined) --------
// Block = 128 thr, 1 row = 128 px x 64 outs; thread tile 8 px x 8 outs.
// Double-buffered A (8192 f each) and B (4096 f each); gather(k+1) is
// software-pipelined against GEMM(k) at sub-chunk granularity (no barrier
// inside a region). smem = 26496 floats = 105984 B -> 2 CTAs/SM.
#define SMF_B0  0
#define SMF_B1  4096
#define SMF_A0  8192
#define SMF_A1  16384
#define SMF_CW  24576
#define SMF_CB  26112
#define SMF_TOT 26496

// prefetch 4 gather-iters (sub-chunk M) for tap KG into q (16 LDG.128)
#define PREFETCH(M, KG) do {                                                  \
    _Pragma("unroll")                                                         \
    for (int ii = 0; ii < 2; ii++) {                                          \
        int i_  = (M)*2 + ii;                                                 \
        int px_ = (wid*8 + i_)*4 + p8;                                        \
        int cv_ = cbase[(KG)*128 + px_];                                      \
        int b00_ = cv_ & 0x00FFFFFF;                                          \
        int dxx_ = ((cv_ >> 24) & 1) << 6;                                    \
        int dyy_ = ((cv_ >> 25) & 1) << 13;                                   \
        int b01_ = b00_ + dxx_, b10_ = b00_ + dyy_, b11_ = b10_ + dxx_;       \
        _Pragma("unroll")                                                     \
        for (int h = 0; h < 2; h++) {                                         \
            int co_ = (h*8 + c8l)*4;                                          \
            q[ii][h][0] = *(const ulonglong2*)(src + b00_ + co_);             \
            q[ii][h][1] = *(const ulonglong2*)(src + b01_ + co_);             \
            q[ii][h][2] = *(const ulonglong2*)(src + b10_ + co_);             \
            q[ii][h][3] = *(const ulonglong2*)(src + b11_ + co_);             \
        }                                                                     \
    }                                                                         \
} while(0)

// combine sub-chunk M's q with corner weights (tap KG) and store to ADST
#define COMBINE_STS(M, KG, ADST) do {                                         \
    _Pragma("unroll")                                                         \
    for (int ii = 0; ii < 2; ii++) {                                          \
        int i_  = (M)*2 + ii;                                                 \
        int pxg_ = wid*8 + i_;                                                \
        int px_ = pxg_*4 + p8;                                                \
        const float* cw_ = &cww[((KG)*128 + px_)*4];                          \
        u64 w00p = pk2(cw_[0], cw_[0]);                                       \
        u64 w01p = pk2(cw_[1], cw_[1]);                                       \
        u64 w10p = pk2(cw_[2], cw_[2]);                                       \
        u64 w11p = pk2(cw_[3], cw_[3]);                                       \
        _Pragma("unroll")                                                     \
        for (int h = 0; h < 2; h++) {                                         \
            int c4g_ = h*8 + c8l;                                             \
            u64 r01 = ffma2(w00p, q[ii][h][0].x, ffma2(w01p, q[ii][h][1].x,   \
                      ffma2(w10p, q[ii][h][2].x, fmul2(w11p, q[ii][h][3].x))));\
            u64 r23 = ffma2(w00p, q[ii][h][0].y, ffma2(w01p, q[ii][h][1].y,   \
                      ffma2(w10p, q[ii][h][2].y, fmul2(w11p, q[ii][h][3].y))));\
            float r0, r1, r2, r3;                                             \
            upk2(r01, r0, r1); upk2(r23, r2, r3);                             \
            int base_ = ((pxg_ ^ (c4g_ & 7)) << 2) + p8;                      \
            float* ar_ = (ADST) + (c4g_*4)*128 + base_;                       \
            ar_[0*128] = r0; ar_[1*128] = r1;                                 \
            ar_[2*128] = r2; ar_[3*128] = r3;                                 \
        }                                                                     \
    }                                                                         \
} while(0)

// GEMM over c in [M*16, M*16+16) reading ASRC/BSRC
#define GEMM_CHUNK(M, ASRC, BSRC) do {                                        \
    _Pragma("unroll")                                                         \
    for (int cc_ = 0; cc_ < 16; cc_++) {                                      \
        int c_ = (M)*16 + cc_;                                                \
        int s_ = (c_ >> 2) & 7;                                               \
        const float* arow_ = (ASRC) + c_*128;                                 \
        float4 a0_ = *(const float4*)(arow_ + (((2*pgr)     ^ s_) << 2));     \
        float4 a1_ = *(const float4*)(arow_ + (((2*pgr + 1) ^ s_) << 2));     \
        const float* brow_ = (BSRC) + c_*64;                                  \
        ulonglong2 bp0_ = *(const ulonglong2*)(brow_ + og*4);                 \
        ulonglong2 bp1_ = *(const ulonglong2*)(brow_ + 32 + og*4);            \
        u64 W0_ = bp0_.x, W1_ = bp0_.y, W2_ = bp1_.x, W3_ = bp1_.y;           \
        _Pragma("unroll")                                                     \
        for (int i_ = 0; i_ < 8; i_++) {                                      \
            float av_ = (i_ < 4) ? f4c(a0_, i_) : f4c(a1_, i_ - 4);           \
            u64 ad_ = pk2(av_, av_);                                          \
            acc[i_][0] = ffma2(ad_, W0_, acc[i_][0]);                         \
            acc[i_][1] = ffma2(ad_, W1_, acc[i_][1]);                         \
            acc[i_][2] = ffma2(ad_, W2_, acc[i_][2]);                         \
            acc[i_][3] = ffma2(ad_, W3_, acc[i_][3]);                         \
        }                                                                     \
    }                                                                         \
} while(0)

template<int VERT, int OUT_NCHW>
__global__ __launch_bounds__(128, 2) void pass_kernel(
    const float* __restrict__ src,   // NHWC input
    const float* __restrict__ om,    // stride-12 offset/mask records
    const float* __restrict__ wB,    // packed weights [3][64][64]
    const float* __restrict__ bias,
    float* __restrict__ dst)
{
    extern __shared__ float smem[];
    float* Bs0  = smem + SMF_B0;
    float* Bs1  = smem + SMF_B1;
    float* As0  = smem + SMF_A0;
    float* As1  = smem + SMF_A1;
    float* cww  = smem + SMF_CW;
    int*  cbase = (int*)(smem + SMF_CB);

    int tid = threadIdx.x, wid = tid >> 5, lane = tid & 31;
    int row = blockIdx.x;            // n*H + y
    int n = row >> 7, y = row & 127;

    // per-pixel, per-tap corner weights + packed base offset
    for (int t = tid; t < 384; t += 128) {
        int k = t >> 7, xp = t & 127;
        const float* omb = om + ((size_t)row*WW + xp)*12;
        float dyk = omb[2*k], dxk = omb[2*k + 1], mkk = omb[6 + k];
        float py = (float)y + dyk + (VERT ? (float)(k-1) : 0.f);
        float pxf = (float)xp + dxk + (VERT ? 0.f : (float)(k-1));
        float y0f = floorf(py), x0f = floorf(pxf);
        float wy = py - y0f, wx = pxf - x0f;
        int iy0 = (int)y0f, ix0 = (int)x0f;
        int iy1 = iy0 + 1,  ix1 = ix0 + 1;
        float vy0 = (iy0 >= 0 && iy0 < HH) ? 1.f : 0.f;
        float vy1 = (iy1 >= 0 && iy1 < HH) ? 1.f : 0.f;
        float vx0 = (ix0 >= 0 && ix0 < WW) ? 1.f : 0.f;
        float vx1 = (ix1 >= 0 && ix1 < WW) ? 1.f : 0.f;
        float* cw = &cww[(k*128 + xp)*4];
        cw[0] = (1.f-wy)*(1.f-wx)*vy0*vx0*mkk;
        cw[1] = (1.f-wy)*wx      *vy0*vx1*mkk;
        cw[2] = wy*(1.f-wx)      *vy1*vx0*mkk;
        cw[3] = wy*wx            *vy1*vx1*mkk;
        int cy0 = min(max(iy0,0),HH-1), cy1 = min(max(iy1,0),HH-1);
        int cx0 = min(max(ix0,0),WW-1), cx1 = min(max(ix1,0),WW-1);
        int b00 = ((n*HH + cy0)*WW + cx0)*CH;     // fits in 23 bits
        int fx = cx1 - cx0;
        int fy = cy1 - cy0;
        cbase[k*128 + xp] = b00 | (fx << 24) | (fy << 25);
    }
    // stage B(0)
    {
        const float4* s4 = (const float4*)wB;
        float4* d4 = (float4*)Bs0;
        #pragma unroll
        for (int i = 0; i < 8; i++)
            d4[tid + i*128] = s4[tid + i*128];
    }
    __syncthreads();

    int p8 = lane >> 3, c8l = lane & 7;     // gather lane roles
    int og = tid & 7, pgr = tid >> 3;       // GEMM: outs og*8.., px pgr*8..

    u64 acc[8][4];
    #pragma unroll
    for (int i = 0; i < 8; i++)
        #pragma unroll
        for (int j = 0; j < 4; j++) acc[i][j] = 0ull;

    ulonglong2 q[2][2][4];

    // prologue: plain gather tap 0 -> As0
    #pragma unroll
    for (int m = 0; m < 4; m++) {
        PREFETCH(m, 0);
        COMBINE_STS(m, 0, As0);
    }
    __syncthreads();

    // pipelined regions: GEMM(k) overlapped with stageB(k+1) + gather(k+1)
    #pragma unroll
    for (int k = 0; k < 2; k++) {
        const float* Asrc = (k & 1) ? As1 : As0;
        float*       Adst = (k & 1) ? As0 : As1;
        const float* Bsrc = (k & 1) ? Bs1 : Bs0;
        float*       Bdst = (k & 1) ? Bs0 : Bs1;
        int kg = k + 1;
        // stage B(k+1)
        {
            const float4* s4 = (const float4*)(wB + kg*4096);
            float4* d4 = (float4*)Bdst;
            #pragma unroll
            for (int i = 0; i < 8; i++)
                d4[tid + i*128] = s4[tid + i*128];
        }
        PREFETCH(0, kg);
        #pragma unroll
        for (int m = 0; m < 4; m++) {
            GEMM_CHUNK(m, Asrc, Bsrc);       // covers PREFETCH(m) latency
            COMBINE_STS(m, kg, Adst);        // LDG results ready now
            if (m < 3) PREFETCH(m+1, kg);    // covered by next GEMM chunk
        }
        __syncthreads();
    }
    // final GEMM tap 2 (buffers: (2&1)=0 -> As0/Bs0)
    #pragma unroll
    for (int m = 0; m < 4; m++)
        GEMM_CHUNK(m, As0, Bs0);

    // -------- epilogue: add bias, store -----------------------------------
    float bv[8];
    #pragma unroll
    for (int mm = 0; mm < 8; mm++) bv[mm] = __ldg(bias + og*8 + mm);

    if (OUT_NCHW) {
        #pragma unroll
        for (int mm = 0; mm < 8; mm++) {
            int j = mm >> 1, t = mm & 1;
            float v[8];
            #pragma unroll
            for (int i = 0; i < 8; i++) {
                float lo, hi; upk2(acc[i][j], lo, hi);
                v[i] = (t ? hi : lo) + bv[mm];
            }
            float* db = dst + (((size_t)(n*CH + og*8 + mm))*HH + y)*WW + pgr*8;
            *(float4*)(db)     = make_float4(v[0], v[1], v[2], v[3]);
            *(float4*)(db + 4) = make_float4(v[4], v[5], v[6], v[7]);
        }
    } else {
        #pragma unroll
        for (int i = 0; i < 8; i++) {
            int px = pgr*8 + i;
            float s[8];
            #pragma unroll
            for (int j = 0; j < 4; j++) {
                float lo, hi; upk2(acc[i][j], lo, hi);
                s[2*j]   = lo + bv[2*j];
                s[2*j+1] = hi + bv[2*j+1];
            }
            float* db = dst + ((size_t)row*WW + px)*CH + og*8;
            *(float4*)(db)     = make_float4(s[0], s[1], s[2], s[3]);
            *(float4*)(db + 4) = make_float4(s[4], s[5], s[6], s[7]);
        }
    }
}

// ---------------- launch ---------------------------------------------------
extern "C" void kernel_launch(void* const* d_in, const int* in_sizes, int n_in,
                              void* d_out, int out_size) {
    const float* x        = (const float*)d_in[0];
    const float* w_off_h  = (const float*)d_in[1];
    const float* b_off_h  = (const float*)d_in[2];
    const float* w_mask_h = (const float*)d_in[3];
    const float* b_mask_h = (const float*)d_in[4];
    const float* w_off_v  = (const float*)d_in[5];
    const float* b_off_v  = (const float*)d_in[6];
    const float* w_mask_v = (const float*)d_in[7];
    const float* b_mask_v = (const float*)d_in[8];
    const float* w_h      = (const float*)d_in[9];
    const float* b_h      = (const float*)d_in[10];
    const float* w_v      = (const float*)d_in[11];
    const float* b_v      = (const float*)d_in[12];
    float* out = (float*)d_out;

    void *xn_p, *xh_p, *omh_p, *omv_p, *wB_p;
    cudaGetSymbolAddress(&xn_p,  g_x_nhwc);
    cudaGetSymbolAddress(&xh_p,  g_xh_nhwc);
    cudaGetSymbolAddress(&omh_p, g_omh);
    cudaGetSymbolAddress(&omv_p, g_omv);
    cudaGetSymbolAddress(&wB_p,  g_wB);
    const float* xn  = (const float*)xn_p;
    float*       xh  = (float*)xh_p;
    const float* omh = (const float*)omh_p;
    const float* omv = (const float*)omv_p;
    const float* wBh = (const float*)wB_p;
    const float* wBv = wBh + 12288;

    int smem_bytes = SMF_TOT * 4;   // 105984 B
    cudaFuncSetAttribute(pass_kernel<0,0>,
                         cudaFuncAttributeMaxDynamicSharedMemorySize, smem_bytes);
    cudaFuncSetAttribute(pass_kernel<1,1>,
                         cudaFuncAttributeMaxDynamicSharedMemorySize, smem_bytes);

    prep_weights<<<96, 256>>>(w_h, w_v);

    transpose_kernel<<<dim3(WW/32, HH, BB), dim3(32, 8)>>>(x);

    offmask_kernel<<<BB*HH/4, 256>>>(w_off_h, b_off_h, w_mask_h, b_mask_h,
                                     w_off_v, b_off_v, w_mask_v, b_mask_v);

    pass_kernel<0, 0><<<BB*HH, 128, smem_bytes>>>(xn, omh, wBh, b_h, xh);
    pass_kernel<1, 1><<<BB*HH, 128, smem_bytes>>>((const float*)xh, omv, wBv, b_v, out);
}

// round 11
// speedup vs baseline: 1.2318x; 1.2318x over previous
#include <cuda_runtime.h>
#include <math.h>
#include <stdint.h>

#define BB 8
#define CH 64
#define HH 128
#define WW 128

typedef unsigned long long u64;

// ---------------- scratch (device globals; no allocation allowed) ----------
__device__ float g_x_nhwc[BB*HH*WW*CH];   // x transposed to NHWC
__device__ float g_xh_nhwc[BB*HH*WW*CH];  // horizontal-pass output, NHWC
__device__ float g_omh[BB*HH*WW*12];      // dy0,dx0,dy1,dx1,dy2,dx2,m0,m1,m2,pad
__device__ float g_omv[BB*HH*WW*12];
// Packed weight images: [pass][k][c][64 floats]; row = 32 u64 out-pairs:
// u64 pos = i2*16 + og*2 + t holds (w[2jg], w[2jg+1]), jg = og*4 + i2*2 + t
__device__ __align__(16) float g_wB[2][12288];

// ---------------- f32x2 packed helpers (Blackwell FFMA2) -------------------
static __device__ __forceinline__ u64 pk2(float a, float b) {
    u64 r; asm("mov.b64 %0, {%1,%2};" : "=l"(r) : "f"(a), "f"(b)); return r;
}
static __device__ __forceinline__ void upk2(u64 v, float &a, float &b) {
    asm("mov.b64 {%0,%1}, %2;" : "=f"(a), "=f"(b) : "l"(v));
}
static __device__ __forceinline__ u64 ffma2(u64 a, u64 b, u64 c) {
    u64 d; asm("fma.rn.f32x2 %0, %1, %2, %3;" : "=l"(d) : "l"(a), "l"(b), "l"(c)); return d;
}
static __device__ __forceinline__ u64 fmul2(u64 a, u64 b) {
    u64 d; asm("mul.rn.f32x2 %0, %1, %2;" : "=l"(d) : "l"(a), "l"(b)); return d;
}
static __device__ __forceinline__ float f4c(const float4 &v, int i) {
    return i == 0 ? v.x : (i == 1 ? v.y : (i == 2 ? v.z : v.w));
}

// ---------------- K-1: weight repack (runs once, tiny) ---------------------
__global__ __launch_bounds__(256) void prep_weights(
    const float* __restrict__ wh, const float* __restrict__ wv)
{
    int i = blockIdx.x*256 + threadIdx.x;
    if (i >= 24576) return;
    int pass = i / 12288;
    int r = i % 12288;
    int k = r / 4096;
    int rr = r % 4096;
    int c = rr / 64;
    int f = rr % 64;
    int pos = f >> 1, e = f & 1;
    int i2 = pos >> 4, og = (pos >> 1) & 7, t = pos & 1;
    int jg = og*4 + i2*2 + t;
    int o = 2*jg + e;
    const float* w = pass ? wv : wh;
    g_wB[pass][r] = w[o*192 + c*3 + k];
}

// ---------------- K0: NCHW -> NHWC transpose -------------------------------
__global__ __launch_bounds__(256) void transpose_kernel(const float* __restrict__ in) {
    __shared__ float tile[CH][33];
    int n = blockIdx.z, y = blockIdx.y, x0 = blockIdx.x * 32;
    int tx = threadIdx.x, ty = threadIdx.y;
    #pragma unroll
    for (int c = ty; c < CH; c += 8)
        tile[c][tx] = in[(((size_t)n*CH + c)*HH + y)*WW + x0 + tx];
    __syncthreads();
    int t = ty*32 + tx;
    #pragma unroll
    for (int i = 0; i < 8; i++) {
        int idx = t + i*256;
        int px = idx >> 6, c = idx & 63;
        g_x_nhwc[(((size_t)n*HH + y)*WW + x0 + px)*CH + c] = tile[c][px];
    }
}

// ---------------- K1: offsets + masks, 2 px (adjacent rows)/thread ---------
__global__ __launch_bounds__(256, 2) void offmask_kernel(
    const float* __restrict__ woh, const float* __restrict__ boh,
    const float* __restrict__ wmh, const float* __restrict__ bmh,
    const float* __restrict__ wov, const float* __restrict__ bov,
    const float* __restrict__ wmv, const float* __restrict__ bmv)
{
    __shared__ float ws[64*6*12];
    int tid = threadIdx.x;
    for (int i = tid; i < 64*6*12; i += 256) {
        int o = i % 12, j = (i/12) % 6, c = i/72;
        float v = 0.f;
        if (o < 6)      v = (j < 3) ? woh[o*192 + c*3 + j] : wov[o*192 + c*3 + (j-3)];
        else if (o < 9) v = (j < 3) ? wmh[(o-6)*192 + c*3 + j] : wmv[(o-6)*192 + c*3 + (j-3)];
        ws[i] = v;
    }
    __syncthreads();

    int x = tid & 127;
    int pairidx = blockIdx.x*2 + (tid >> 7);
    int row0 = pairidx*2;
    int y = row0 & 127;
    size_t p0 = (size_t)row0*WW + x;
    size_t p1 = p0 + WW;

    u64 H0a=0,H0b=0,H0c=0,H0d=0, V0a=0,V0b=0,V0c=0,V0d=0;
    u64 H1a=0,H1b=0,H1c=0,H1d=0, V1a=0,V1b=0,V1c=0,V1d=0;
    float H0e=0.f, V0e=0.f, H1e=0.f, V1e=0.f;

    const float* pc0 = g_x_nhwc + p0*CH;
    const float* pc1 = g_x_nhwc + p1*CH;
    bool hl = x > 0, hr = x < WW-1;
    bool vu = y > 0, vd = (y + 2) < HH;
    const float* pl0 = pc0 - CH;
    const float* pr0 = pc0 + CH;
    const float* pl1 = pc1 - CH;
    const float* pr1 = pc1 + CH;
    const float* pu  = pc0 - (size_t)WW*CH;
    const float* pd  = pc1 + (size_t)WW*CH;
    const float4 Z = make_float4(0.f,0.f,0.f,0.f);

    for (int c4 = 0; c4 < 16; c4++) {
        float4 fc0 = *(const float4*)(pc0 + c4*4);
        float4 fc1 = *(const float4*)(pc1 + c4*4);
        float4 fl0 = hl ? *(const float4*)(pl0 + c4*4) : Z;
        float4 fr0 = hr ? *(const float4*)(pr0 + c4*4) : Z;
        float4 fl1 = hl ? *(const float4*)(pl1 + c4*4) : Z;
        float4 fr1 = hr ? *(const float4*)(pr1 + c4*4) : Z;
        float4 fu  = vu ? *(const float4*)(pu  + c4*4) : Z;
        float4 fd  = vd ? *(const float4*)(pd  + c4*4) : Z;
        #pragma unroll
        for (int cc = 0; cc < 4; cc++) {
            int c = c4*4 + cc;
            float h0[3] = { f4c(fl0,cc), f4c(fc0,cc), f4c(fr0,cc) };
            float h1[3] = { f4c(fl1,cc), f4c(fc1,cc), f4c(fr1,cc) };
            float v0[3] = { f4c(fu,cc),  f4c(fc0,cc), f4c(fc1,cc) };
            float v1[3] = { f4c(fc0,cc), f4c(fc1,cc), f4c(fd,cc)  };
            #pragma unroll
            for (int j = 0; j < 3; j++) {
                const float* wb = &ws[(c*6 + j)*12];
                ulonglong2 W0 = *(const ulonglong2*)(wb);
                ulonglong2 W1 = *(const ulonglong2*)(wb + 4);
                float w8 = wb[8];
                u64 s0 = pk2(h0[j], h0[j]);
                H0a = ffma2(s0, W0.x, H0a); H0b = ffma2(s0, W0.y, H0b);
                H0c = ffma2(s0, W1.x, H0c); H0d = ffma2(s0, W1.y, H0d);
                H0e = fmaf(h0[j], w8, H0e);
                u64 s1 = pk2(h1[j], h1[j]);
                H1a = ffma2(s1, W0.x, H1a); H1b = ffma2(s1, W0.y, H1b);
                H1c = ffma2(s1, W1.x, H1c); H1d = ffma2(s1, W1.y, H1d);
                H1e = fmaf(h1[j], w8, H1e);

                const float* ub = &ws[(c*6 + j + 3)*12];
                ulonglong2 U0 = *(const ulonglong2*)(ub);
                ulonglong2 U1 = *(const ulonglong2*)(ub + 4);
                float u8 = ub[8];
                u64 t0 = pk2(v0[j], v0[j]);
                V0a = ffma2(t0, U0.x, V0a); V0b = ffma2(t0, U0.y, V0b);
                V0c = ffma2(t0, U1.x, V0c); V0d = ffma2(t0, U1.y, V0d);
                V0e = fmaf(v0[j], u8, V0e);
                u64 t1 = pk2(v1[j], v1[j]);
                V1a = ffma2(t1, U0.x, V1a); V1b = ffma2(t1, U0.y, V1b);
                V1c = ffma2(t1, U1.x, V1c); V1d = ffma2(t1, U1.y, V1d);
                V1e = fmaf(v1[j], u8, V1e);
            }
        }
    }

    float b0 = __ldg(boh+0), b1 = __ldg(boh+1), b2 = __ldg(boh+2);
    float b3 = __ldg(boh+3), b4 = __ldg(boh+4), b5 = __ldg(boh+5);
    float c0 = __ldg(bov+0), c1 = __ldg(bov+1), c2 = __ldg(bov+2);
    float c3 = __ldg(bov+3), c4b = __ldg(bov+4), c5 = __ldg(bov+5);
    float mb0 = __ldg(bmh+0), mb1 = __ldg(bmh+1), mb2 = __ldg(bmh+2);
    float nb0 = __ldg(bmv+0), nb1 = __ldg(bmv+1), nb2 = __ldg(bmv+2);

    #pragma unroll
    for (int r = 0; r < 2; r++) {
        float A[9], V[9];
        if (r == 0) {
            upk2(H0a,A[0],A[1]); upk2(H0b,A[2],A[3]); upk2(H0c,A[4],A[5]);
            upk2(H0d,A[6],A[7]); A[8]=H0e;
            upk2(V0a,V[0],V[1]); upk2(V0b,V[2],V[3]); upk2(V0c,V[4],V[5]);
            upk2(V0d,V[6],V[7]); V[8]=V0e;
        } else {
            upk2(H1a,A[0],A[1]); upk2(H1b,A[2],A[3]); upk2(H1c,A[4],A[5]);
            upk2(H1d,A[6],A[7]); A[8]=H1e;
            upk2(V1a,V[0],V[1]); upk2(V1b,V[2],V[3]); upk2(V1c,V[4],V[5]);
            upk2(V1d,V[6],V[7]); V[8]=V1e;
        }
        size_t p = r ? p1 : p0;
        float mh0 = 1.f/(1.f + expf(-(A[6] + mb0)));
        float mh1 = 1.f/(1.f + expf(-(A[7] + mb1)));
        float mh2 = 1.f/(1.f + expf(-(A[8] + mb2)));
        float mv0 = 1.f/(1.f + expf(-(V[6] + nb0)));
        float mv1 = 1.f/(1.f + expf(-(V[7] + nb1)));
        float mv2 = 1.f/(1.f + expf(-(V[8] + nb2)));
        float* oh = g_omh + p*12;
        *(float4*)(oh+0) = make_float4(A[0]+b0, A[1]+b1, A[2]+b2, A[3]+b3);
        *(float4*)(oh+4) = make_float4(A[4]+b4, A[5]+b5, mh0, mh1);
        oh[8] = mh2;
        float* ov = g_omv + p*12;
        *(float4*)(ov+0) = make_float4(V[0]+c0, V[1]+c1, V[2]+c2, V[3]+c3);
        *(float4*)(ov+4) = make_float4(V[4]+c4b, V[5]+c5, mv0, mv1);
        ov[8] = mv2;
    }
}

// ---------------- K2/K3: deformable axial pass (warp-specialized) ----------
// Block = 256 thr: threads 0-127 = producers (gather + B staging),
// threads 128-255 = consumers (GEMM, 8 px x 8 outs each).
// Double-buffered A (2x8192 f) and B (2x4096 f); one __syncthreads per tap.
// smem = 26496 floats = 105984 B -> 2 CTAs/SM.
#define SMF_B0  0
#define SMF_B1  4096
#define SMF_A0  8192
#define SMF_A1  16384
#define SMF_CW  24576
#define SMF_CB  26112
#define SMF_TOT 26496

template<int VERT, int OUT_NCHW>
__global__ __launch_bounds__(256, 2) void pass_kernel(
    const float* __restrict__ src,   // NHWC input
    const float* __restrict__ om,    // stride-12 offset/mask records
    const float* __restrict__ wB,    // packed weights [3][64][64]
    const float* __restrict__ bias,
    float* __restrict__ dst)
{
    extern __shared__ float smem[];
    float* Bbuf[2] = { smem + SMF_B0, smem + SMF_B1 };
    float* Abuf[2] = { smem + SMF_A0, smem + SMF_A1 };
    float* cww  = smem + SMF_CW;
    int*  cbase = (int*)(smem + SMF_CB);

    int tid = threadIdx.x;
    int row = blockIdx.x;            // n*H + y
    int n = row >> 7, y = row & 127;
    bool producer = tid < 128;

    // ---- prologue: corner weights/offsets (all threads) -------------------
    for (int t = tid; t < 384; t += 256) {
        int k = t >> 7, xp = t & 127;
        const float* omb = om + ((size_t)row*WW + xp)*12;
        float dyk = omb[2*k], dxk = omb[2*k + 1], mkk = omb[6 + k];
        float py = (float)y + dyk + (VERT ? (float)(k-1) : 0.f);
        float pxf = (float)xp + dxk + (VERT ? 0.f : (float)(k-1));
        float y0f = floorf(py), x0f = floorf(pxf);
        float wy = py - y0f, wx = pxf - x0f;
        int iy0 = (int)y0f, ix0 = (int)x0f;
        int iy1 = iy0 + 1,  ix1 = ix0 + 1;
        float vy0 = (iy0 >= 0 && iy0 < HH) ? 1.f : 0.f;
        float vy1 = (iy1 >= 0 && iy1 < HH) ? 1.f : 0.f;
        float vx0 = (ix0 >= 0 && ix0 < WW) ? 1.f : 0.f;
        float vx1 = (ix1 >= 0 && ix1 < WW) ? 1.f : 0.f;
        float* cw = &cww[(k*128 + xp)*4];
        cw[0] = (1.f-wy)*(1.f-wx)*vy0*vx0*mkk;
        cw[1] = (1.f-wy)*wx      *vy0*vx1*mkk;
        cw[2] = wy*(1.f-wx)      *vy1*vx0*mkk;
        cw[3] = wy*wx            *vy1*vx1*mkk;
        int cy0 = min(max(iy0,0),HH-1), cy1 = min(max(iy1,0),HH-1);
        int cx0 = min(max(ix0,0),WW-1), cx1 = min(max(ix1,0),WW-1);
        int b00 = ((n*HH + cy0)*WW + cx0)*CH;     // fits in 23 bits
        int fx = cx1 - cx0;
        int fy = cy1 - cy0;
        cbase[k*128 + xp] = b00 | (fx << 24) | (fy << 25);
    }
    // stage B(0) (all 256 threads)
    {
        const float4* s4 = (const float4*)wB;
        float4* d4 = (float4*)Bbuf[0];
        #pragma unroll
        for (int i = 0; i < 4; i++)
            d4[tid + i*256] = s4[tid + i*256];
    }
    __syncthreads();

    // producer roles
    int wid = tid >> 5, lane = tid & 31;
    int p8 = lane >> 3, c8l = lane & 7;
    // consumer roles
    int ctid = tid - 128;
    int og = ctid & 7, pgr = ctid >> 3;

    u64 acc[8][4];
    #pragma unroll
    for (int i = 0; i < 8; i++)
        #pragma unroll
        for (int j = 0; j < 4; j++) acc[i][j] = 0ull;

    // producers: gather tap 0 -> A0
    if (producer) {
        #pragma unroll
        for (int i = 0; i < 8; i++) {
            int pxg = wid*8 + i;
            int px = pxg*4 + p8;
            const float* cw = &cww[px*4];
            int cv = cbase[px];
            u64 w00p = pk2(cw[0], cw[0]);
            u64 w01p = pk2(cw[1], cw[1]);
            u64 w10p = pk2(cw[2], cw[2]);
            u64 w11p = pk2(cw[3], cw[3]);
            int b00 = cv & 0x00FFFFFF;
            int dx = ((cv >> 24) & 1) << 6;
            int dy = ((cv >> 25) & 1) << 13;
            int b01 = b00 + dx, b10 = b00 + dy, b11 = b10 + dx;
            #pragma unroll
            for (int h = 0; h < 2; h++) {
                int c4g = h*8 + c8l;
                int co = c4g*4;
                ulonglong2 q00 = *(const ulonglong2*)(src + b00 + co);
                ulonglong2 q01 = *(const ulonglong2*)(src + b01 + co);
                ulonglong2 q10 = *(const ulonglong2*)(src + b10 + co);
                ulonglong2 q11 = *(const ulonglong2*)(src + b11 + co);
                u64 r01 = ffma2(w00p, q00.x, ffma2(w01p, q01.x,
                          ffma2(w10p, q10.x, fmul2(w11p, q11.x))));
                u64 r23 = ffma2(w00p, q00.y, ffma2(w01p, q01.y,
                          ffma2(w10p, q10.y, fmul2(w11p, q11.y))));
                float r0, r1, r2, r3;
                upk2(r01, r0, r1); upk2(r23, r2, r3);
                int base = ((pxg ^ (c4g & 7)) << 2) + p8;
                float* ar = Abuf[0] + co*128 + base;
                ar[0*128] = r0; ar[1*128] = r1;
                ar[2*128] = r2; ar[3*128] = r3;
            }
        }
    }
    __syncthreads();

    // ---- pipelined taps: producers fill (k+1) while consumers GEMM (k) ----
    #pragma unroll
    for (int k = 0; k < 3; k++) {
        if (producer) {
            if (k < 2) {
                int kg = k + 1;
                int bsel = kg & 1;
                // stage B(kg)
                {
                    const float4* s4 = (const float4*)(wB + kg*4096);
                    float4* d4 = (float4*)Bbuf[bsel];
                    #pragma unroll
                    for (int i = 0; i < 8; i++)
                        d4[tid + i*128] = s4[tid + i*128];
                }
                // gather tap kg -> Abuf[bsel]
                #pragma unroll
                for (int i = 0; i < 8; i++) {
                    int pxg = wid*8 + i;
                    int px = pxg*4 + p8;
                    const float* cw = &cww[(kg*128 + px)*4];
                    int cv = cbase[kg*128 + px];
                    u64 w00p = pk2(cw[0], cw[0]);
                    u64 w01p = pk2(cw[1], cw[1]);
                    u64 w10p = pk2(cw[2], cw[2]);
                    u64 w11p = pk2(cw[3], cw[3]);
                    int b00 = cv & 0x00FFFFFF;
                    int dx = ((cv >> 24) & 1) << 6;
                    int dy = ((cv >> 25) & 1) << 13;
                    int b01 = b00 + dx, b10 = b00 + dy, b11 = b10 + dx;
                    #pragma unroll
                    for (int h = 0; h < 2; h++) {
                        int c4g = h*8 + c8l;
                        int co = c4g*4;
                        ulonglong2 q00 = *(const ulonglong2*)(src + b00 + co);
                        ulonglong2 q01 = *(const ulonglong2*)(src + b01 + co);
                        ulonglong2 q10 = *(const ulonglong2*)(src + b10 + co);
                        ulonglong2 q11 = *(const ulonglong2*)(src + b11 + co);
                        u64 r01 = ffma2(w00p, q00.x, ffma2(w01p, q01.x,
                                  ffma2(w10p, q10.x, fmul2(w11p, q11.x))));
                        u64 r23 = ffma2(w00p, q00.y, ffma2(w01p, q01.y,
                                  ffma2(w10p, q10.y, fmul2(w11p, q11.y))));
                        float r0, r1, r2, r3;
                        upk2(r01, r0, r1); upk2(r23, r2, r3);
                        int base = ((pxg ^ (c4g & 7)) << 2) + p8;
                        float* ar = Abuf[bsel] + co*128 + base;
                        ar[0*128] = r0; ar[1*128] = r1;
                        ar[2*128] = r2; ar[3*128] = r3;
                    }
                }
            }
        } else {
            // consumers: GEMM tap k
            const float* As = Abuf[k & 1];
            const float* Bs = Bbuf[k & 1];
            #pragma unroll 4
            for (int c = 0; c < 64; c++) {
                int s = (c >> 2) & 7;
                const float* arow = As + c*128;
                float4 a0 = *(const float4*)(arow + (((2*pgr)     ^ s) << 2));
                float4 a1 = *(const float4*)(arow + (((2*pgr + 1) ^ s) << 2));
                const float* brow = Bs + c*64;
                ulonglong2 bp0 = *(const ulonglong2*)(brow + og*4);
                ulonglong2 bp1 = *(const ulonglong2*)(brow + 32 + og*4);
                u64 W0 = bp0.x, W1 = bp0.y, W2 = bp1.x, W3 = bp1.y;
                #pragma unroll
                for (int i = 0; i < 8; i++) {
                    float av = (i < 4) ? f4c(a0, i) : f4c(a1, i - 4);
                    u64 ad = pk2(av, av);
                    acc[i][0] = ffma2(ad, W0, acc[i][0]);
                    acc[i][1] = ffma2(ad, W1, acc[i][1]);
                    acc[i][2] = ffma2(ad, W2, acc[i][2]);
                    acc[i][3] = ffma2(ad, W3, acc[i][3]);
                }
            }
        }
        __syncthreads();
    }

    // ---- epilogue: consumers add bias + store -----------------------------
    if (!producer) {
        float bv[8];
        #pragma unroll
        for (int m = 0; m < 8; m++) bv[m] = __ldg(bias + og*8 + m);

        if (OUT_NCHW) {
            #pragma unroll
            for (int m = 0; m < 8; m++) {
                int j = m >> 1, t = m & 1;
                float v[8];
                #pragma unroll
                for (int i = 0; i < 8; i++) {
                    float lo, hi; upk2(acc[i][j], lo, hi);
                    v[i] = (t ? hi : lo) + bv[m];
                }
                float* db = dst + (((size_t)(n*CH + og*8 + m))*HH + y)*WW + pgr*8;
                *(float4*)(db)     = make_float4(v[0], v[1], v[2], v[3]);
                *(float4*)(db + 4) = make_float4(v[4], v[5], v[6], v[7]);
            }
        } else {
            #pragma unroll
            for (int i = 0; i < 8; i++) {
                int px = pgr*8 + i;
                float s[8];
                #pragma unroll
                for (int j = 0; j < 4; j++) {
                    float lo, hi; upk2(acc[i][j], lo, hi);
                    s[2*j]   = lo + bv[2*j];
                    s[2*j+1] = hi + bv[2*j+1];
                }
                float* db = dst + ((size_t)row*WW + px)*CH + og*8;
                *(float4*)(db)     = make_float4(s[0], s[1], s[2], s[3]);
                *(float4*)(db + 4) = make_float4(s[4], s[5], s[6], s[7]);
            }
        }
    }
}

// ---------------- launch ---------------------------------------------------
extern "C" void kernel_launch(void* const* d_in, const int* in_sizes, int n_in,
                              void* d_out, int out_size) {
    const float* x        = (const float*)d_in[0];
    const float* w_off_h  = (const float*)d_in[1];
    const float* b_off_h  = (const float*)d_in[2];
    const float* w_mask_h = (const float*)d_in[3];
    const float* b_mask_h = (const float*)d_in[4];
    const float* w_off_v  = (const float*)d_in[5];
    const float* b_off_v  = (const float*)d_in[6];
    const float* w_mask_v = (const float*)d_in[7];
    const float* b_mask_v = (const float*)d_in[8];
    const float* w_h      = (const float*)d_in[9];
    const float* b_h      = (const float*)d_in[10];
    const float* w_v      = (const float*)d_in[11];
    const float* b_v      = (const float*)d_in[12];
    float* out = (float*)d_out;

    void *xn_p, *xh_p, *omh_p, *omv_p, *wB_p;
    cudaGetSymbolAddress(&xn_p,  g_x_nhwc);
    cudaGetSymbolAddress(&xh_p,  g_xh_nhwc);
    cudaGetSymbolAddress(&omh_p, g_omh);
    cudaGetSymbolAddress(&omv_p, g_omv);
    cudaGetSymbolAddress(&wB_p,  g_wB);
    const float* xn  = (const float*)xn_p;
    float*       xh  = (float*)xh_p;
    const float* omh = (const float*)omh_p;
    const float* omv = (const float*)omv_p;
    const float* wBh = (const float*)wB_p;
    const float* wBv = wBh + 12288;

    int smem_bytes = SMF_TOT * 4;   // 105984 B
    cudaFuncSetAttribute(pass_kernel<0,0>,
                         cudaFuncAttributeMaxDynamicSharedMemorySize, smem_bytes);
    cudaFuncSetAttribute(pass_kernel<1,1>,
                         cudaFuncAttributeMaxDynamicSharedMemorySize, smem_bytes);

    prep_weights<<<96, 256>>>(w_h, w_v);

    transpose_kernel<<<dim3(WW/32, HH, BB), dim3(32, 8)>>>(x);

    offmask_kernel<<<BB*HH/4, 256>>>(w_off_h, b_off_h, w_mask_h, b_mask_h,
                                     w_off_v, b_off_v, w_mask_v, b_mask_v);

    pass_kernel<0, 0><<<BB*HH, 256, smem_bytes>>>(xn, omh, wBh, b_h, xh);
    pass_kernel<1, 1><<<BB*HH, 256, smem_bytes>>>((const float*)xh, omv, wBv, b_v, out);
}